// round 11
// baseline (speedup 1.0000x reference)
#include <cuda_runtime.h>
#include <cstdint>

// CenterLoss collapses: the mask is one-hot per row and clip() lifts the
// masked-out zeros to exactly 1e-12, so
//   loss = (1/B) * sum_b clamp(||x_b - c_{label_b}||^2, 1e-12, 1e12)
//          + (NUM_CLASSES - 1) * 1e-12
// Only 4096 gathered squared distances are needed (16.8 MB read).
// Single fused kernel: last-block-done reduction (counter auto-wraps, so the
// kernel is graph-replayable with no reset pass).
// FINAL: fastest measured mode (8.672 us, reproduced three times: R4/R5/R10).
// Session falsified occupancy (20-80%), MLP (8-16), grid (256-1024), and tail
// restructurings as levers — the floor is graph-replay/launch overhead.

#define CL_BATCH       4096
#define CL_DIM         512
#define CL_NUM_CLASSES 10000
#define CL_WARPS       8                       // samples per block (1 warp each)
#define CL_THREADS     (CL_WARPS * 32)         // 256
#define CL_NBLOCKS     (CL_BATCH / CL_WARPS)   // 512

__device__ float        g_cl_partials[CL_NBLOCKS];
__device__ unsigned int g_cl_count = 0;

// Robust label fetch: labels may be stored as int64 or int32. For int64
// (values < 10000) every odd 32-bit word is the zero high-half; for int32
// the odd words are random labels. 8 odd words all-zero => int64, with
// misclassification probability ~1e-32.
__device__ __forceinline__ int cl_load_label(const int* __restrict__ lw, int b) {
    int or_acc = 0;
#pragma unroll
    for (int i = 0; i < 8; ++i) or_acc |= lw[2 * i + 1];
    return (or_acc == 0) ? lw[2 * b] : lw[b];
}

__global__ __launch_bounds__(CL_THREADS)
void centerloss_fused_kernel(const float* __restrict__ x,
                             const int* __restrict__ label_words,
                             const float* __restrict__ centers,
                             float* __restrict__ out) {
    const int warp = threadIdx.x >> 5;
    const int lane = threadIdx.x & 31;
    const int b = blockIdx.x * CL_WARPS + warp;

    int lbl = 0;
    if (lane == 0) lbl = cl_load_label(label_words, b);
    lbl = __shfl_sync(0xffffffffu, lbl, 0);

    const float4* __restrict__ xr =
        reinterpret_cast<const float4*>(x + (size_t)b * CL_DIM);
    const float4* __restrict__ cr =
        reinterpret_cast<const float4*>(centers + (size_t)lbl * CL_DIM);

    // One warp per sample: 512 floats -> 16 per lane -> 4x float4 per side.
    float acc = 0.0f;
#pragma unroll
    for (int i = 0; i < 4; ++i) {
        const float4 a = xr[lane + i * 32];
        const float4 c = cr[lane + i * 32];
        const float d0 = a.x - c.x;
        const float d1 = a.y - c.y;
        const float d2 = a.z - c.z;
        const float d3 = a.w - c.w;
        acc = fmaf(d0, d0, acc);
        acc = fmaf(d1, d1, acc);
        acc = fmaf(d2, d2, acc);
        acc = fmaf(d3, d3, acc);
    }

#pragma unroll
    for (int o = 16; o > 0; o >>= 1)
        acc += __shfl_xor_sync(0xffffffffu, acc, o);

    __shared__ float s[CL_WARPS];
    if (lane == 0) {
        // clamp exactly like the reference clip(dist, 1e-12, 1e12)
        s[warp] = fminf(fmaxf(acc, 1e-12f), 1e12f);
    }
    __syncthreads();

    // Block partial + last-block election.
    __shared__ bool is_last;
    if (threadIdx.x == 0) {
        float t = 0.0f;
#pragma unroll
        for (int i = 0; i < CL_WARPS; ++i) t += s[i];
        g_cl_partials[blockIdx.x] = t;
        __threadfence();
        // atomicInc wraps old==511 -> 0, so the counter is reset for the
        // next graph replay automatically.
        unsigned int prev = atomicInc(&g_cl_count, CL_NBLOCKS - 1);
        is_last = (prev == CL_NBLOCKS - 1);
    }
    __syncthreads();

    // Last block reduces all 512 partials in double (fixed order -> deterministic).
    if (is_last) {
        __shared__ double sd[CL_THREADS];
        const int t = threadIdx.x;
        sd[t] = (double)g_cl_partials[t] + (double)g_cl_partials[t + CL_THREADS];
        __syncthreads();
#pragma unroll
        for (int stride = CL_THREADS / 2; stride > 32; stride >>= 1) {
            if (t < stride) sd[t] += sd[t + stride];
            __syncthreads();
        }
        if (t < 32) {
            double v = sd[t] + sd[t + 32];
#pragma unroll
            for (int o = 16; o > 0; o >>= 1)
                v += __shfl_xor_sync(0xffffffffu, v, o);
            if (t == 0) {
                // + (C - 1) * 1e-12 per row from clamped zeros (B rows / B)
                const double zeros_term = (double)(CL_NUM_CLASSES - 1) * 1e-12;
                out[0] = (float)(v / (double)CL_BATCH + zeros_term);
            }
        }
    }
}

extern "C" void kernel_launch(void* const* d_in, const int* in_sizes, int n_in,
                              void* d_out, int out_size) {
    // Identify inputs by unique element counts instead of trusting order:
    //   x: 4096*512 = 2097152, centers: 10000*512 = 5120000, labels: 4096.
    const float* x       = nullptr;
    const float* centers = nullptr;
    const int*   labels  = nullptr;
    for (int i = 0; i < n_in; ++i) {
        if (in_sizes[i] == CL_BATCH * CL_DIM)            x       = (const float*)d_in[i];
        else if (in_sizes[i] == CL_NUM_CLASSES * CL_DIM) centers = (const float*)d_in[i];
        else if (in_sizes[i] == CL_BATCH)                labels  = (const int*)d_in[i];
    }
    if (!x)       x       = (const float*)d_in[0];
    if (!labels)  labels  = (const int*)d_in[1];
    if (!centers) centers = (const float*)d_in[2];

    centerloss_fused_kernel<<<CL_NBLOCKS, CL_THREADS>>>(
        x, labels, centers, (float*)d_out);
}